// round 3
// baseline (speedup 1.0000x reference)
#include <cuda_runtime.h>
#include <math.h>

// ---------------------------------------------------------------------------
// SmoothAP (quick_forward, sigmoid rank approx, 1-mAP), B x B scores/target.
//
// Key algebra:
//   ap[b] = (1/npos_b) * sum_{i : target[b,i]=1} (P_i + 0.5) / (A_i + 0.5)
// where, with s = scores[b,:], tg = target[b,:]:
//   A_i = sum_j sigmoid((s_j - s_i)/tau)           (unmasked; 0.5 diag folded)
//   P_i = sum_j sigmoid((s_j - s_i)/tau) * tg_j    (target row i == row b when
//                                                   target[b,i]==1)
// out = 1 - (1/B) * sum_b ap[b]
// ---------------------------------------------------------------------------

#define INV_TAU 100.0f   // 1 / 0.01

__device__ float g_accum;

__global__ void sap_init_kernel() { g_accum = 0.0f; }

__global__ void sap_main_kernel(const float* __restrict__ scores,
                                const float* __restrict__ target,
                                int B) {
    extern __shared__ float sh[];
    float* ss = sh;          // scores row  [B]
    float* st = sh + B;      // target row  [B]

    const int b = blockIdx.x;
    const float* srow = scores + (size_t)b * B;
    const float* trow = target + (size_t)b * B;

    for (int j = threadIdx.x; j < B; j += blockDim.x) {
        ss[j] = srow[j];
        st[j] = trow[j];
    }
    __syncthreads();

    const int lane   = threadIdx.x & 31;
    const int warp   = threadIdx.x >> 5;
    const int nwarps = blockDim.x >> 5;

    // npos_b = sum_j target[b,j]  (redundant per warp; cheap)
    float np = 0.0f;
    for (int j = lane; j < B; j += 32) np += st[j];
#pragma unroll
    for (int o = 16; o; o >>= 1) np += __shfl_xor_sync(0xffffffffu, np, o);

    float sum_r = 0.0f;
    for (int i = warp; i < B; i += nwarps) {
        if (st[i] == 0.0f) continue;      // uniform across warp
        const float si = ss[i];
        float A = 0.0f, P = 0.0f;
        for (int j = lane; j < B; j += 32) {
            // sigmoid((s_j - s_i)/tau) = 1 / (1 + exp((s_i - s_j)/tau))
            float e  = __expf((si - ss[j]) * INV_TAU);
            float sg = __fdividef(1.0f, 1.0f + e);
            A += sg;
            P = fmaf(sg, st[j], P);
        }
#pragma unroll
        for (int o = 16; o; o >>= 1) {
            A += __shfl_xor_sync(0xffffffffu, A, o);
            P += __shfl_xor_sync(0xffffffffu, P, o);
        }
        // diag term (j==i): sg=0.5 exactly, tg_i=1.  sim_all = A-0.5+1,
        // sim_pos = P-0.5+1 (the "+target" term and "*target" factor are 1).
        sum_r += (P + 0.5f) / (A + 0.5f);
    }

    if (lane == 0 && sum_r != 0.0f)
        atomicAdd(&g_accum, sum_r / np);
}

__global__ void sap_fini_kernel(float* __restrict__ out, int B) {
    out[0] = 1.0f - g_accum / (float)B;
}

extern "C" void kernel_launch(void* const* d_in, const int* in_sizes, int n_in,
                              void* d_out, int out_size) {
    const float* scores = (const float*)d_in[0];
    const float* target = (const float*)d_in[1];
    float* out = (float*)d_out;

    // B*B = in_sizes[0]
    int n = in_sizes[0];
    int B = 1;
    while ((long long)B * B < (long long)n) ++B;

    int threads = 512;
    if (threads > B) {
        threads = ((B + 31) / 32) * 32;
        if (threads < 32) threads = 32;
    }
    size_t smem = (size_t)2 * B * sizeof(float);

    sap_init_kernel<<<1, 1>>>();
    sap_main_kernel<<<B, threads, smem>>>(scores, target, B);
    sap_fini_kernel<<<1, 1>>>(out, B);
}